// round 12
// baseline (speedup 1.0000x reference)
#include <cuda_runtime.h>
#include <cuda_fp16.h>
#include <cstdint>
#include <math.h>

#define NB   16
#define NF   64
#define GC   64
#define KK   8
#define HH   96
#define WW   96
#define HW   (HH*WW)
#define CTOT 320

// ---------------------------------------------------------------------------
// Scratch
// ---------------------------------------------------------------------------
__device__ __half g_concat[(size_t)NB * HW * CTOT];      // NHWC fp16
__device__ float  g_pooled[NB * CTOT];
__device__ float  g_attn[NB * KK];
__device__ float  g_bk[NB * GC];
__device__ __half g_wk2h[(size_t)NB * 9 * GC * CTOT];    // [b][tap][oc][c] fp16
__device__ float  g_partial[(size_t)NB * 144 * 64];      // GAP partials per tile

// ---------------------------------------------------------------------------
// NCHW fp32 -> NHWC fp16 transpose of input x, fused GAP partials (fp32).
// grid (144, 16), block 256.
// ---------------------------------------------------------------------------
__global__ void copyx_t(const float* __restrict__ x) {
    __shared__ float sm[64][65];
    __shared__ float red[4][64];
    int b = blockIdx.y;
    int p0 = blockIdx.x * 64;
    int t = threadIdx.x;
    #pragma unroll
    for (int i = 0; i < 16; i++) {
        int idx = t + i * 256;
        int c = idx >> 6, pl = idx & 63;
        sm[c][pl] = x[((size_t)b * 64 + c) * HW + p0 + pl];
    }
    __syncthreads();
    const int c = t & 63;
    float s = 0.f;
    #pragma unroll
    for (int i = 0; i < 16; i++) {
        int pl = (t >> 6) + 4 * i;
        float v = sm[c][pl];
        g_concat[((size_t)b * HW + p0 + pl) * CTOT + c] = __float2half(v);
        s += v;
    }
    red[t >> 6][c] = s;
    __syncthreads();
    if (t < 64)
        g_partial[((size_t)b * 144 + blockIdx.x) * 64 + t] =
            red[0][t] + red[1][t] + red[2][t] + red[3][t];
}

// ---------------------------------------------------------------------------
// Attention MLP per sample, with fused GAP-partial reduction for the newest
// 64 channels. grid(NB), block 128.
// ---------------------------------------------------------------------------
template <int CIN>
__global__ void attn_kernel(const float* __restrict__ aw1, const float* __restrict__ ab1,
                            const float* __restrict__ aw2, const float* __restrict__ ab2,
                            const float* __restrict__ bvec, int ntiles, int ch_off) {
    const int HID = CIN / 4;
    int b = blockIdx.x;
    int t = threadIdx.x;
    __shared__ float red[2][64];
    __shared__ float sp[CIN];
    __shared__ float sh[HID];
    __shared__ float sl[KK];
    __shared__ float sa[KK];

    {
        int ch = t & 63, grp = t >> 6;
        float s = 0.f;
        for (int tile = grp; tile < ntiles; tile += 2)
            s += g_partial[((size_t)b * 144 + tile) * 64 + ch];
        red[grp][ch] = s;
        __syncthreads();
        if (t < 64)
            g_pooled[b * CTOT + ch_off + t] = (red[0][t] + red[1][t]) * (1.f / (float)HW);
        __syncthreads();
    }

    for (int i = t; i < CIN; i += 128) sp[i] = g_pooled[b * CTOT + i];
    __syncthreads();
    if (t < HID) {
        float s = ab1[t];
        const float* row = aw1 + (size_t)t * CIN;
        for (int c = 0; c < CIN; c++) s += row[c] * sp[c];
        sh[t] = s > 0.f ? s : 0.f;
    }
    __syncthreads();
    if (t < KK) {
        float s = ab2[t];
        const float* row = aw2 + (size_t)t * HID;
        for (int j = 0; j < HID; j++) s += row[j] * sh[j];
        sl[t] = s;
    }
    __syncthreads();
    if (t == 0) {
        float m = sl[0];
        for (int k = 1; k < KK; k++) m = fmaxf(m, sl[k]);
        float den = 0.f;
        for (int k = 0; k < KK; k++) { float e = expf(sl[k] - m); sa[k] = e; den += e; }
        float inv = 1.f / den;
        for (int k = 0; k < KK; k++) { sa[k] *= inv; g_attn[b * KK + k] = sa[k]; }
    }
    __syncthreads();
    if (t < GC) {
        float s = 0.f;
        #pragma unroll
        for (int k = 0; k < KK; k++) s += sa[k] * bvec[k * GC + t];
        g_bk[b * GC + t] = s;
    }
}

// ---------------------------------------------------------------------------
// Batched weight mixing: thread owns (oc, c-pair), loads all 8 experts once,
// applies all 16 attention vectors. grid: (64*CIN/2)/128, block 128.
// ---------------------------------------------------------------------------
template <int CIN>
__global__ __launch_bounds__(128)
void mix2h_batched(const float* __restrict__ w) {
    __shared__ float s_attn[NB][KK];
    int t = threadIdx.x;
    if (t < NB * KK) s_attn[t / KK][t % KK] = g_attn[t];
    __syncthreads();

    int idx = blockIdx.x * 128 + t;
    const int NPC = CIN / 2;
    if (idx >= GC * NPC) return;
    int oc = idx / NPC;
    int cp = idx - oc * NPC;
    int cc = cp * 2;

    float wreg[KK][18];
    #pragma unroll
    for (int k = 0; k < KK; k++) {
        const float* src = w + (((size_t)k * GC + oc) * CIN + cc) * 9;
        #pragma unroll
        for (int j = 0; j < 18; j++) wreg[k][j] = src[j];
    }

    #pragma unroll 1
    for (int b = 0; b < NB; b++) {
        float a[KK];
        #pragma unroll
        for (int k = 0; k < KK; k++) a[k] = s_attn[b][k];
        float s[18];
        #pragma unroll
        for (int j = 0; j < 18; j++) {
            float v = 0.f;
            #pragma unroll
            for (int k = 0; k < KK; k++) v += a[k] * wreg[k][j];
            s[j] = v;
        }
        __half* dst = g_wk2h + (size_t)b * (9 * GC * CIN);
        #pragma unroll
        for (int tap = 0; tap < 9; tap++) {
            *(__half2*)&dst[(((size_t)tap * GC + oc) * CIN) + cc] =
                __floats2half2_rn(s[tap], s[tap + 9]);
        }
    }
}

// ---------------------------------------------------------------------------
// fp16 mma.sync conv, cp.async double-buffered chunks + software-pipelined
// fragment loads (double-buffered af/bf across 18 steps per chunk).
// CTA: 384 pixels (12 rows x 32 cols) x 64 oc. 12 warps, each 32px x 64oc.
// grid (3, 8, NB), block 384, dynamic smem 2*84160 = 168320.
// ---------------------------------------------------------------------------
#define APAD 40
#define A_ROWS 476                              // 14 x 34 halo rows
#define B_ROWS 576
#define A_BYTES (A_ROWS * APAD * 2)             // 38080
#define STAGE_BYTES (A_BYTES + B_ROWS * APAD * 2)  // 84160
#define CONV_SMEM (2 * STAGE_BYTES)             // 168320

__device__ __forceinline__ void mma_16816(float* c, const uint32_t* a, const uint32_t* b) {
    asm volatile(
        "mma.sync.aligned.m16n8k16.row.col.f32.f16.f16.f32 "
        "{%0,%1,%2,%3}, {%4,%5,%6,%7}, {%8,%9}, {%0,%1,%2,%3};"
        : "+f"(c[0]), "+f"(c[1]), "+f"(c[2]), "+f"(c[3])
        : "r"(a[0]), "r"(a[1]), "r"(a[2]), "r"(a[3]), "r"(b[0]), "r"(b[1]));
}

__device__ __forceinline__ void ldsm_x4(uint32_t* r, uint32_t saddr) {
    asm volatile("ldmatrix.sync.aligned.m8n8.x4.shared.b16 {%0,%1,%2,%3}, [%4];"
                 : "=r"(r[0]), "=r"(r[1]), "=r"(r[2]), "=r"(r[3]) : "r"(saddr));
}

__device__ __forceinline__ void cp_async16(uint32_t dst, const void* src, int src_sz) {
    asm volatile("cp.async.cg.shared.global [%0], [%1], 16, %2;"
                 :: "r"(dst), "l"(src), "r"(src_sz) : "memory");
}
#define CP_COMMIT() asm volatile("cp.async.commit_group;" ::: "memory")
#define CP_WAIT0()  asm volatile("cp.async.wait_group 0;" ::: "memory")

template <int CIN, bool FINAL>
__global__ __launch_bounds__(384, 1)
void conv_mma(float* __restrict__ dout, const float* __restrict__ xres, int out_ch_off) {
    extern __shared__ __align__(16) char dyn[];
    __shared__ float s_bias[64];
    __shared__ float s_red[12][64];

    const int t = threadIdx.x;
    const int lane = t & 31;
    const int wid = t >> 5;                 // 0..11 -> image row within tile
    const int gx0 = blockIdx.x * 32;
    const int gy0 = blockIdx.y * 12;
    const int b = blockIdx.z;
    const int NC = CIN / 32;

    const uint32_t su = (uint32_t)__cvta_generic_to_shared(dyn);
    const __half* inb = g_concat + (size_t)b * HW * CTOT;
    const __half* wkb = g_wk2h + (size_t)b * (9 * GC * CIN);

    if (t < 64) s_bias[t] = g_bk[b * GC + t];

    float acc[2][8][4];
    #pragma unroll
    for (int mt = 0; mt < 2; mt++)
        #pragma unroll
        for (int nt = 0; nt < 8; nt++)
            #pragma unroll
            for (int q = 0; q < 4; q++) acc[mt][nt][q] = 0.f;

    auto issue_chunk = [&](int c0, int stage) {
        uint32_t sbase = su + stage * STAGE_BYTES;
        // A: 476 halo rows x 4 segs = 1904
        #pragma unroll
        for (int k = 0; k < 5; k++) {
            int i = t + k * 384;
            if (i < A_ROWS * 4) {
                int row = i >> 2, q = i & 3;
                int r = row / 34, cc = row - r * 34;
                int gy = gy0 + r - 1, gx = gx0 + cc - 1;
                bool ok = ((unsigned)gy < HH) && ((unsigned)gx < WW);
                const __half* src = ok ? (inb + (size_t)(gy * WW + gx) * CTOT + c0 + q * 8)
                                       : inb;
                cp_async16(sbase + (row * APAD + q * 8) * 2, src, ok ? 16 : 0);
            }
        }
        // B: 576 rows x 4 segs = 2304 = 384*6
        #pragma unroll
        for (int k = 0; k < 6; k++) {
            int i = t + k * 384;
            int row = i >> 2, q = i & 3;
            const __half* src = wkb + (size_t)row * CIN + c0 + q * 8;
            cp_async16(sbase + A_BYTES + (row * APAD + q * 8) * 2, src, 16);
        }
    };

    issue_chunk(0, 0);
    CP_COMMIT();

    const int a_m  = lane & 15;
    const int a_kh = lane >> 4;
    const int b_n  = (lane >> 4) * 8 + (lane & 7);
    const int b_kh = (lane >> 3) & 1;

    uint32_t af[2][2][4];   // [buf][mt][frag]
    uint32_t bf[2][8][2];   // [buf][nt][frag]

    #pragma unroll 1
    for (int ic = 0; ic < NC; ic++) {
        const int s = ic & 1;
        const uint32_t sa_u = su + s * STAGE_BYTES;
        const uint32_t sb_u = sa_u + A_BYTES;

        CP_WAIT0();
        __syncthreads();     // stage s full; orders prior readers of s^1
        if (ic + 1 < NC) {
            issue_chunk((ic + 1) * 32, s ^ 1);
            CP_COMMIT();
        }

        // fragment loader for step = tap*2 + k16
        auto load_step = [&](int step, uint32_t (*afd)[4], uint32_t (*bfd)[2]) {
            const int tap = step >> 1, k16 = step & 1;
            const int dy = tap / 3 - 1, dx = tap % 3 - 1;
            const int arow = (wid + dy + 1) * 34 + dx + 1;
            #pragma unroll
            for (int mt = 0; mt < 2; mt++) {
                uint32_t addr = sa_u + 2 * ((arow + mt * 16 + a_m) * APAD + k16 * 16 + a_kh * 8);
                ldsm_x4(afd[mt], addr);
            }
            const uint32_t btap = sb_u + (tap * 64) * (APAD * 2);
            #pragma unroll
            for (int j = 0; j < 4; j++) {
                uint32_t r[4];
                int n = j * 16 + b_n;
                uint32_t addr = btap + 2 * (n * APAD + k16 * 16 + b_kh * 8);
                ldsm_x4(r, addr);
                bfd[j * 2][0] = r[0]; bfd[j * 2][1] = r[1];
                bfd[j * 2 + 1][0] = r[2]; bfd[j * 2 + 1][1] = r[3];
            }
        };

        load_step(0, af[0], bf[0]);
        #pragma unroll 1
        for (int step = 0; step < 18; step++) {
            const int cur = step & 1;
            if (step < 17) load_step(step + 1, af[cur ^ 1], bf[cur ^ 1]);
            #pragma unroll
            for (int mt = 0; mt < 2; mt++)
                #pragma unroll
                for (int nt = 0; nt < 8; nt++)
                    mma_16816(acc[mt][nt], af[cur][mt], bf[cur][nt]);
        }
        // next iteration's top barrier orders stage overwrite
    }

    // epilogue (+ fused GAP partials)
    const int gy = gy0 + wid;
    float sum0[8], sum1[8];
    #pragma unroll
    for (int nt = 0; nt < 8; nt++) { sum0[nt] = 0.f; sum1[nt] = 0.f; }

    #pragma unroll
    for (int mt = 0; mt < 2; mt++) {
        #pragma unroll
        for (int hi = 0; hi < 2; hi++) {
            int px = mt * 16 + (lane >> 2) + hi * 8;
            size_t pixidx = (size_t)gy * WW + gx0 + px;
            #pragma unroll
            for (int nt = 0; nt < 8; nt++) {
                int oc = nt * 8 + 2 * (lane & 3);
                float v0 = acc[mt][nt][hi * 2 + 0] + s_bias[oc];
                float v1 = acc[mt][nt][hi * 2 + 1] + s_bias[oc + 1];
                if (FINAL) {
                    dout[((size_t)b * GC + oc) * HW + pixidx] =
                        0.2f * v0 + xres[((size_t)b * GC + oc) * HW + pixidx];
                    dout[((size_t)b * GC + oc + 1) * HW + pixidx] =
                        0.2f * v1 + xres[((size_t)b * GC + oc + 1) * HW + pixidx];
                } else {
                    v0 = v0 >= 0.f ? v0 : 0.2f * v0;
                    v1 = v1 >= 0.f ? v1 : 0.2f * v1;
                    *(__half2*)&g_concat[((size_t)b * HW + pixidx) * CTOT + out_ch_off + oc] =
                        __floats2half2_rn(v0, v1);
                    sum0[nt] += v0;
                    sum1[nt] += v1;
                }
            }
        }
    }

    if (!FINAL) {
        #pragma unroll
        for (int nt = 0; nt < 8; nt++) {
            #pragma unroll
            for (int off = 16; off >= 4; off >>= 1) {
                sum0[nt] += __shfl_xor_sync(0xFFFFFFFFu, sum0[nt], off);
                sum1[nt] += __shfl_xor_sync(0xFFFFFFFFu, sum1[nt], off);
            }
        }
        if (lane < 4) {
            #pragma unroll
            for (int nt = 0; nt < 8; nt++) {
                int chl = nt * 8 + 2 * lane;
                s_red[wid][chl]     = sum0[nt];
                s_red[wid][chl + 1] = sum1[nt];
            }
        }
        __syncthreads();
        if (t < 64) {
            int tile = blockIdx.y * 3 + blockIdx.x;
            float s = 0.f;
            #pragma unroll
            for (int wv = 0; wv < 12; wv++) s += s_red[wv][t];
            g_partial[((size_t)b * 144 + tile) * 64 + t] = s;
        }
    }
}

// ---------------------------------------------------------------------------
// Host orchestration
// ---------------------------------------------------------------------------
extern "C" void kernel_launch(void* const* d_in, const int* in_sizes, int n_in,
                              void* d_out, int out_size) {
    const float* x = (const float*)d_in[0];
    const float *W[5], *Bv[5], *A1[5], *Ab1[5], *A2[5], *Ab2[5];
    for (int i = 0; i < 5; i++) {
        W[i]   = (const float*)d_in[1 + 6 * i + 0];
        Bv[i]  = (const float*)d_in[1 + 6 * i + 1];
        A1[i]  = (const float*)d_in[1 + 6 * i + 2];
        Ab1[i] = (const float*)d_in[1 + 6 * i + 3];
        A2[i]  = (const float*)d_in[1 + 6 * i + 4];
        Ab2[i] = (const float*)d_in[1 + 6 * i + 5];
    }
    float* out = (float*)d_out;

    cudaFuncSetAttribute(conv_mma<64,  false>, cudaFuncAttributeMaxDynamicSharedMemorySize, CONV_SMEM);
    cudaFuncSetAttribute(conv_mma<128, false>, cudaFuncAttributeMaxDynamicSharedMemorySize, CONV_SMEM);
    cudaFuncSetAttribute(conv_mma<192, false>, cudaFuncAttributeMaxDynamicSharedMemorySize, CONV_SMEM);
    cudaFuncSetAttribute(conv_mma<256, false>, cudaFuncAttributeMaxDynamicSharedMemorySize, CONV_SMEM);
    cudaFuncSetAttribute(conv_mma<320, true >, cudaFuncAttributeMaxDynamicSharedMemorySize, CONV_SMEM);

    dim3 cgrid(3, 8, NB);

    copyx_t<<<dim3(144, NB), 256>>>(x);

    // Layer 1 (cin=64)
    attn_kernel<64><<<NB, 128>>>(A1[0], Ab1[0], A2[0], Ab2[0], Bv[0], 144, 0);
    mix2h_batched<64><<<(GC * 32 + 127) / 128, 128>>>(W[0]);
    conv_mma<64, false><<<cgrid, 384, CONV_SMEM>>>(nullptr, nullptr, 64);

    // Layer 2 (cin=128)
    attn_kernel<128><<<NB, 128>>>(A1[1], Ab1[1], A2[1], Ab2[1], Bv[1], 24, 64);
    mix2h_batched<128><<<(GC * 64 + 127) / 128, 128>>>(W[1]);
    conv_mma<128, false><<<cgrid, 384, CONV_SMEM>>>(nullptr, nullptr, 128);

    // Layer 3 (cin=192)
    attn_kernel<192><<<NB, 128>>>(A1[2], Ab1[2], A2[2], Ab2[2], Bv[2], 24, 128);
    mix2h_batched<192><<<(GC * 96 + 127) / 128, 128>>>(W[2]);
    conv_mma<192, false><<<cgrid, 384, CONV_SMEM>>>(nullptr, nullptr, 192);

    // Layer 4 (cin=256)
    attn_kernel<256><<<NB, 128>>>(A1[3], Ab1[3], A2[3], Ab2[3], Bv[3], 24, 192);
    mix2h_batched<256><<<(GC * 128 + 127) / 128, 128>>>(W[3]);
    conv_mma<256, false><<<cgrid, 384, CONV_SMEM>>>(nullptr, nullptr, 256);

    // Layer 5 (cin=320) -> final output with fp32 residual from original x
    attn_kernel<320><<<NB, 128>>>(A1[4], Ab1[4], A2[4], Ab2[4], Bv[4], 24, 256);
    mix2h_batched<320><<<(GC * 160 + 127) / 128, 128>>>(W[4]);
    conv_mma<320, true><<<cgrid, 384, CONV_SMEM>>>(out, x, 0);
}

// round 13
// speedup vs baseline: 2.5041x; 2.5041x over previous
#include <cuda_runtime.h>
#include <cuda_fp16.h>
#include <cstdint>
#include <math.h>

#define NB   16
#define NF   64
#define GC   64
#define KK   8
#define HH   96
#define WW   96
#define HW   (HH*WW)
#define CTOT 320

// ---------------------------------------------------------------------------
// Scratch
// ---------------------------------------------------------------------------
__device__ __half g_concat[(size_t)NB * HW * CTOT];      // NHWC fp16
__device__ float  g_pooled[NB * CTOT];
__device__ float  g_attn[NB * KK];
__device__ float  g_bk[NB * GC];
__device__ __half g_wk2h[(size_t)NB * 9 * GC * CTOT];    // [b][tap][oc][c] fp16
__device__ float  g_partial[(size_t)NB * 144 * 64];      // GAP partials per tile

// ---------------------------------------------------------------------------
// NCHW fp32 -> NHWC fp16 transpose of input x, fused GAP partials (fp32).
// grid (144, 16), block 256.
// ---------------------------------------------------------------------------
__global__ void copyx_t(const float* __restrict__ x) {
    __shared__ float sm[64][65];
    __shared__ float red[4][64];
    int b = blockIdx.y;
    int p0 = blockIdx.x * 64;
    int t = threadIdx.x;
    #pragma unroll
    for (int i = 0; i < 16; i++) {
        int idx = t + i * 256;
        int c = idx >> 6, pl = idx & 63;
        sm[c][pl] = x[((size_t)b * 64 + c) * HW + p0 + pl];
    }
    __syncthreads();
    const int c = t & 63;
    float s = 0.f;
    #pragma unroll
    for (int i = 0; i < 16; i++) {
        int pl = (t >> 6) + 4 * i;
        float v = sm[c][pl];
        g_concat[((size_t)b * HW + p0 + pl) * CTOT + c] = __float2half(v);
        s += v;
    }
    red[t >> 6][c] = s;
    __syncthreads();
    if (t < 64)
        g_partial[((size_t)b * 144 + blockIdx.x) * 64 + t] =
            red[0][t] + red[1][t] + red[2][t] + red[3][t];
}

// ---------------------------------------------------------------------------
// Attention MLP per sample, with fused GAP-partial reduction for the newest
// 64 channels. grid(NB), block 128.
// ---------------------------------------------------------------------------
template <int CIN>
__global__ void attn_kernel(const float* __restrict__ aw1, const float* __restrict__ ab1,
                            const float* __restrict__ aw2, const float* __restrict__ ab2,
                            const float* __restrict__ bvec, int ntiles, int ch_off) {
    const int HID = CIN / 4;
    int b = blockIdx.x;
    int t = threadIdx.x;
    __shared__ float red[2][64];
    __shared__ float sp[CIN];
    __shared__ float sh[HID];
    __shared__ float sl[KK];
    __shared__ float sa[KK];

    {
        int ch = t & 63, grp = t >> 6;
        float s = 0.f;
        for (int tile = grp; tile < ntiles; tile += 2)
            s += g_partial[((size_t)b * 144 + tile) * 64 + ch];
        red[grp][ch] = s;
        __syncthreads();
        if (t < 64)
            g_pooled[b * CTOT + ch_off + t] = (red[0][t] + red[1][t]) * (1.f / (float)HW);
        __syncthreads();
    }

    for (int i = t; i < CIN; i += 128) sp[i] = g_pooled[b * CTOT + i];
    __syncthreads();
    if (t < HID) {
        float s = ab1[t];
        const float* row = aw1 + (size_t)t * CIN;
        for (int c = 0; c < CIN; c++) s += row[c] * sp[c];
        sh[t] = s > 0.f ? s : 0.f;
    }
    __syncthreads();
    if (t < KK) {
        float s = ab2[t];
        const float* row = aw2 + (size_t)t * HID;
        for (int j = 0; j < HID; j++) s += row[j] * sh[j];
        sl[t] = s;
    }
    __syncthreads();
    if (t == 0) {
        float m = sl[0];
        for (int k = 1; k < KK; k++) m = fmaxf(m, sl[k]);
        float den = 0.f;
        for (int k = 0; k < KK; k++) { float e = expf(sl[k] - m); sa[k] = e; den += e; }
        float inv = 1.f / den;
        for (int k = 0; k < KK; k++) { sa[k] *= inv; g_attn[b * KK + k] = sa[k]; }
    }
    __syncthreads();
    if (t < GC) {
        float s = 0.f;
        #pragma unroll
        for (int k = 0; k < KK; k++) s += sa[k] * bvec[k * GC + t];
        g_bk[b * GC + t] = s;
    }
}

// ---------------------------------------------------------------------------
// Batched weight mixing: thread owns (oc, c-pair), loads all 8 experts once,
// applies all 16 attention vectors. grid: (64*CIN/2)/128, block 128.
// ---------------------------------------------------------------------------
template <int CIN>
__global__ __launch_bounds__(128)
void mix2h_batched(const float* __restrict__ w) {
    __shared__ float s_attn[NB][KK];
    int t = threadIdx.x;
    if (t < NB * KK) s_attn[t / KK][t % KK] = g_attn[t];
    __syncthreads();

    int idx = blockIdx.x * 128 + t;
    const int NPC = CIN / 2;
    if (idx >= GC * NPC) return;
    int oc = idx / NPC;
    int cp = idx - oc * NPC;
    int cc = cp * 2;

    float wreg[KK][18];
    #pragma unroll
    for (int k = 0; k < KK; k++) {
        const float* src = w + (((size_t)k * GC + oc) * CIN + cc) * 9;
        #pragma unroll
        for (int j = 0; j < 18; j++) wreg[k][j] = src[j];
    }

    #pragma unroll 1
    for (int b = 0; b < NB; b++) {
        float a[KK];
        #pragma unroll
        for (int k = 0; k < KK; k++) a[k] = s_attn[b][k];
        float s[18];
        #pragma unroll
        for (int j = 0; j < 18; j++) {
            float v = 0.f;
            #pragma unroll
            for (int k = 0; k < KK; k++) v += a[k] * wreg[k][j];
            s[j] = v;
        }
        __half* dst = g_wk2h + (size_t)b * (9 * GC * CIN);
        #pragma unroll
        for (int tap = 0; tap < 9; tap++) {
            *(__half2*)&dst[(((size_t)tap * GC + oc) * CIN) + cc] =
                __floats2half2_rn(s[tap], s[tap + 9]);
        }
    }
}

// ---------------------------------------------------------------------------
// fp16 mma.sync conv, cp.async double-buffered chunks + software-pipelined
// fragment loads. Fragment buffers are STATICALLY named (af0/bf0, af1/bf1);
// the 18 steps per chunk are processed in pairs so all indices are
// compile-time -> fragments stay in registers (R12's dynamic-index bug fixed).
// CTA: 384 pixels (12 rows x 32 cols) x 64 oc. 12 warps, each 32px x 64oc.
// grid (3, 8, NB), block 384, dynamic smem 2*84160 = 168320.
// ---------------------------------------------------------------------------
#define APAD 40
#define A_ROWS 476                              // 14 x 34 halo rows
#define B_ROWS 576
#define A_BYTES (A_ROWS * APAD * 2)             // 38080
#define STAGE_BYTES (A_BYTES + B_ROWS * APAD * 2)  // 84160
#define CONV_SMEM (2 * STAGE_BYTES)             // 168320

__device__ __forceinline__ void mma_16816(float* c, const uint32_t* a, const uint32_t* b) {
    asm volatile(
        "mma.sync.aligned.m16n8k16.row.col.f32.f16.f16.f32 "
        "{%0,%1,%2,%3}, {%4,%5,%6,%7}, {%8,%9}, {%0,%1,%2,%3};"
        : "+f"(c[0]), "+f"(c[1]), "+f"(c[2]), "+f"(c[3])
        : "r"(a[0]), "r"(a[1]), "r"(a[2]), "r"(a[3]), "r"(b[0]), "r"(b[1]));
}

__device__ __forceinline__ void ldsm_x4(uint32_t* r, uint32_t saddr) {
    asm volatile("ldmatrix.sync.aligned.m8n8.x4.shared.b16 {%0,%1,%2,%3}, [%4];"
                 : "=r"(r[0]), "=r"(r[1]), "=r"(r[2]), "=r"(r[3]) : "r"(saddr));
}

__device__ __forceinline__ void cp_async16(uint32_t dst, const void* src, int src_sz) {
    asm volatile("cp.async.cg.shared.global [%0], [%1], 16, %2;"
                 :: "r"(dst), "l"(src), "r"(src_sz) : "memory");
}
#define CP_COMMIT() asm volatile("cp.async.commit_group;" ::: "memory")
#define CP_WAIT0()  asm volatile("cp.async.wait_group 0;" ::: "memory")

template <int CIN, bool FINAL>
__global__ __launch_bounds__(384, 1)
void conv_mma(float* __restrict__ dout, const float* __restrict__ xres, int out_ch_off) {
    extern __shared__ __align__(16) char dyn[];
    __shared__ float s_bias[64];
    __shared__ float s_red[12][64];

    const int t = threadIdx.x;
    const int lane = t & 31;
    const int wid = t >> 5;                 // 0..11 -> image row within tile
    const int gx0 = blockIdx.x * 32;
    const int gy0 = blockIdx.y * 12;
    const int b = blockIdx.z;
    const int NC = CIN / 32;

    const uint32_t su = (uint32_t)__cvta_generic_to_shared(dyn);
    const __half* inb = g_concat + (size_t)b * HW * CTOT;
    const __half* wkb = g_wk2h + (size_t)b * (9 * GC * CIN);

    if (t < 64) s_bias[t] = g_bk[b * GC + t];

    float acc[2][8][4];
    #pragma unroll
    for (int mt = 0; mt < 2; mt++)
        #pragma unroll
        for (int nt = 0; nt < 8; nt++)
            #pragma unroll
            for (int q = 0; q < 4; q++) acc[mt][nt][q] = 0.f;

    auto issue_chunk = [&](int c0, int stage) {
        uint32_t sbase = su + stage * STAGE_BYTES;
        #pragma unroll
        for (int k = 0; k < 5; k++) {
            int i = t + k * 384;
            if (i < A_ROWS * 4) {
                int row = i >> 2, q = i & 3;
                int r = row / 34, cc = row - r * 34;
                int gy = gy0 + r - 1, gx = gx0 + cc - 1;
                bool ok = ((unsigned)gy < HH) && ((unsigned)gx < WW);
                const __half* src = ok ? (inb + (size_t)(gy * WW + gx) * CTOT + c0 + q * 8)
                                       : inb;
                cp_async16(sbase + (row * APAD + q * 8) * 2, src, ok ? 16 : 0);
            }
        }
        #pragma unroll
        for (int k = 0; k < 6; k++) {
            int i = t + k * 384;
            int row = i >> 2, q = i & 3;
            const __half* src = wkb + (size_t)row * CIN + c0 + q * 8;
            cp_async16(sbase + A_BYTES + (row * APAD + q * 8) * 2, src, 16);
        }
    };

    issue_chunk(0, 0);
    CP_COMMIT();

    const int a_m  = lane & 15;
    const int a_kh = lane >> 4;
    const int b_n  = (lane >> 4) * 8 + (lane & 7);
    const int b_kh = (lane >> 3) & 1;

    // statically-named fragment double buffers (always registers)
    uint32_t af0[2][4], af1[2][4];
    uint32_t bf0[8][2], bf1[8][2];

    #pragma unroll 1
    for (int ic = 0; ic < NC; ic++) {
        const int s = ic & 1;
        const uint32_t sa_u = su + s * STAGE_BYTES;
        const uint32_t sb_u = sa_u + A_BYTES;

        CP_WAIT0();
        __syncthreads();     // stage s full; orders prior readers of s^1
        if (ic + 1 < NC) {
            issue_chunk((ic + 1) * 32, s ^ 1);
            CP_COMMIT();
        }

        // fragment loader: step = tap*2 + k16. Destination arrays are passed
        // by reference and statically named at each call site.
        auto load_step = [&](int step, uint32_t (&afd)[2][4], uint32_t (&bfd)[8][2]) {
            const int tap = step >> 1, k16 = step & 1;
            const int dy = tap / 3 - 1, dx = tap % 3 - 1;
            const int arow = (wid + dy + 1) * 34 + dx + 1;
            #pragma unroll
            for (int mt = 0; mt < 2; mt++) {
                uint32_t addr = sa_u + 2 * ((arow + mt * 16 + a_m) * APAD + k16 * 16 + a_kh * 8);
                ldsm_x4(afd[mt], addr);
            }
            const uint32_t btap = sb_u + (tap * 64) * (APAD * 2);
            #pragma unroll
            for (int j = 0; j < 4; j++) {
                uint32_t r[4];
                int n = j * 16 + b_n;
                uint32_t addr = btap + 2 * (n * APAD + k16 * 16 + b_kh * 8);
                ldsm_x4(r, addr);
                bfd[j * 2][0] = r[0]; bfd[j * 2][1] = r[1];
                bfd[j * 2 + 1][0] = r[2]; bfd[j * 2 + 1][1] = r[3];
            }
        };
        auto mma_block = [&](uint32_t (&afd)[2][4], uint32_t (&bfd)[8][2]) {
            #pragma unroll
            for (int mt = 0; mt < 2; mt++)
                #pragma unroll
                for (int nt = 0; nt < 8; nt++)
                    mma_16816(acc[mt][nt], afd[mt], bfd[nt]);
        };

        load_step(0, af0, bf0);
        #pragma unroll 1
        for (int sp = 0; sp < 9; sp++) {       // 9 pairs = 18 steps
            const int e = sp * 2;
            load_step(e + 1, af1, bf1);        // prefetch odd step
            mma_block(af0, bf0);               // compute even step
            if (sp < 8) load_step(e + 2, af0, bf0);  // prefetch next even
            mma_block(af1, bf1);               // compute odd step
        }
        // next iteration's top barrier orders stage overwrite
    }

    // epilogue (+ fused GAP partials)
    const int gy = gy0 + wid;
    float sum0[8], sum1[8];
    #pragma unroll
    for (int nt = 0; nt < 8; nt++) { sum0[nt] = 0.f; sum1[nt] = 0.f; }

    #pragma unroll
    for (int mt = 0; mt < 2; mt++) {
        #pragma unroll
        for (int hi = 0; hi < 2; hi++) {
            int px = mt * 16 + (lane >> 2) + hi * 8;
            size_t pixidx = (size_t)gy * WW + gx0 + px;
            #pragma unroll
            for (int nt = 0; nt < 8; nt++) {
                int oc = nt * 8 + 2 * (lane & 3);
                float v0 = acc[mt][nt][hi * 2 + 0] + s_bias[oc];
                float v1 = acc[mt][nt][hi * 2 + 1] + s_bias[oc + 1];
                if (FINAL) {
                    dout[((size_t)b * GC + oc) * HW + pixidx] =
                        0.2f * v0 + xres[((size_t)b * GC + oc) * HW + pixidx];
                    dout[((size_t)b * GC + oc + 1) * HW + pixidx] =
                        0.2f * v1 + xres[((size_t)b * GC + oc + 1) * HW + pixidx];
                } else {
                    v0 = v0 >= 0.f ? v0 : 0.2f * v0;
                    v1 = v1 >= 0.f ? v1 : 0.2f * v1;
                    *(__half2*)&g_concat[((size_t)b * HW + pixidx) * CTOT + out_ch_off + oc] =
                        __floats2half2_rn(v0, v1);
                    sum0[nt] += v0;
                    sum1[nt] += v1;
                }
            }
        }
    }

    if (!FINAL) {
        #pragma unroll
        for (int nt = 0; nt < 8; nt++) {
            #pragma unroll
            for (int off = 16; off >= 4; off >>= 1) {
                sum0[nt] += __shfl_xor_sync(0xFFFFFFFFu, sum0[nt], off);
                sum1[nt] += __shfl_xor_sync(0xFFFFFFFFu, sum1[nt], off);
            }
        }
        if (lane < 4) {
            #pragma unroll
            for (int nt = 0; nt < 8; nt++) {
                int chl = nt * 8 + 2 * lane;
                s_red[wid][chl]     = sum0[nt];
                s_red[wid][chl + 1] = sum1[nt];
            }
        }
        __syncthreads();
        if (t < 64) {
            int tile = blockIdx.y * 3 + blockIdx.x;
            float s = 0.f;
            #pragma unroll
            for (int wv = 0; wv < 12; wv++) s += s_red[wv][t];
            g_partial[((size_t)b * 144 + tile) * 64 + t] = s;
        }
    }
}

// ---------------------------------------------------------------------------
// Host orchestration
// ---------------------------------------------------------------------------
extern "C" void kernel_launch(void* const* d_in, const int* in_sizes, int n_in,
                              void* d_out, int out_size) {
    const float* x = (const float*)d_in[0];
    const float *W[5], *Bv[5], *A1[5], *Ab1[5], *A2[5], *Ab2[5];
    for (int i = 0; i < 5; i++) {
        W[i]   = (const float*)d_in[1 + 6 * i + 0];
        Bv[i]  = (const float*)d_in[1 + 6 * i + 1];
        A1[i]  = (const float*)d_in[1 + 6 * i + 2];
        Ab1[i] = (const float*)d_in[1 + 6 * i + 3];
        A2[i]  = (const float*)d_in[1 + 6 * i + 4];
        Ab2[i] = (const float*)d_in[1 + 6 * i + 5];
    }
    float* out = (float*)d_out;

    cudaFuncSetAttribute(conv_mma<64,  false>, cudaFuncAttributeMaxDynamicSharedMemorySize, CONV_SMEM);
    cudaFuncSetAttribute(conv_mma<128, false>, cudaFuncAttributeMaxDynamicSharedMemorySize, CONV_SMEM);
    cudaFuncSetAttribute(conv_mma<192, false>, cudaFuncAttributeMaxDynamicSharedMemorySize, CONV_SMEM);
    cudaFuncSetAttribute(conv_mma<256, false>, cudaFuncAttributeMaxDynamicSharedMemorySize, CONV_SMEM);
    cudaFuncSetAttribute(conv_mma<320, true >, cudaFuncAttributeMaxDynamicSharedMemorySize, CONV_SMEM);

    dim3 cgrid(3, 8, NB);

    copyx_t<<<dim3(144, NB), 256>>>(x);

    // Layer 1 (cin=64)
    attn_kernel<64><<<NB, 128>>>(A1[0], Ab1[0], A2[0], Ab2[0], Bv[0], 144, 0);
    mix2h_batched<64><<<(GC * 32 + 127) / 128, 128>>>(W[0]);
    conv_mma<64, false><<<cgrid, 384, CONV_SMEM>>>(nullptr, nullptr, 64);

    // Layer 2 (cin=128)
    attn_kernel<128><<<NB, 128>>>(A1[1], Ab1[1], A2[1], Ab2[1], Bv[1], 24, 64);
    mix2h_batched<128><<<(GC * 64 + 127) / 128, 128>>>(W[1]);
    conv_mma<128, false><<<cgrid, 384, CONV_SMEM>>>(nullptr, nullptr, 128);

    // Layer 3 (cin=192)
    attn_kernel<192><<<NB, 128>>>(A1[2], Ab1[2], A2[2], Ab2[2], Bv[2], 24, 128);
    mix2h_batched<192><<<(GC * 96 + 127) / 128, 128>>>(W[2]);
    conv_mma<192, false><<<cgrid, 384, CONV_SMEM>>>(nullptr, nullptr, 192);

    // Layer 4 (cin=256)
    attn_kernel<256><<<NB, 128>>>(A1[3], Ab1[3], A2[3], Ab2[3], Bv[3], 24, 192);
    mix2h_batched<256><<<(GC * 128 + 127) / 128, 128>>>(W[3]);
    conv_mma<256, false><<<cgrid, 384, CONV_SMEM>>>(nullptr, nullptr, 256);

    // Layer 5 (cin=320) -> final output with fp32 residual from original x
    attn_kernel<320><<<NB, 128>>>(A1[4], Ab1[4], A2[4], Ab2[4], Bv[4], 24, 256);
    mix2h_batched<320><<<(GC * 160 + 127) / 128, 128>>>(W[4]);
    conv_mma<320, true><<<cgrid, 384, CONV_SMEM>>>(out, x, 0);
}

// round 14
// speedup vs baseline: 2.8084x; 1.1215x over previous
#include <cuda_runtime.h>
#include <cuda_fp16.h>
#include <cstdint>
#include <math.h>

#define NB   16
#define NF   64
#define GC   64
#define KK   8
#define HH   96
#define WW   96
#define HW   (HH*WW)
#define CTOT 320

// ---------------------------------------------------------------------------
// Scratch
// ---------------------------------------------------------------------------
__device__ __half g_concat[(size_t)NB * HW * CTOT];      // NHWC fp16
__device__ float  g_pooled[NB * CTOT];
__device__ float  g_attn[NB * KK];
__device__ float  g_bk[NB * GC];
__device__ __half g_wk2h[(size_t)NB * 9 * GC * CTOT];    // [b][tap][oc][c] fp16
__device__ float  g_partial[(size_t)NB * 144 * 64];      // GAP partials per tile

// ---------------------------------------------------------------------------
// NCHW fp32 -> NHWC fp16 transpose of input x, fused GAP partials (fp32).
// grid (144, 16), block 256.
// ---------------------------------------------------------------------------
__global__ void copyx_t(const float* __restrict__ x) {
    __shared__ float sm[64][65];
    __shared__ float red[4][64];
    int b = blockIdx.y;
    int p0 = blockIdx.x * 64;
    int t = threadIdx.x;
    #pragma unroll
    for (int i = 0; i < 16; i++) {
        int idx = t + i * 256;
        int c = idx >> 6, pl = idx & 63;
        sm[c][pl] = x[((size_t)b * 64 + c) * HW + p0 + pl];
    }
    __syncthreads();
    const int c = t & 63;
    float s = 0.f;
    #pragma unroll
    for (int i = 0; i < 16; i++) {
        int pl = (t >> 6) + 4 * i;
        float v = sm[c][pl];
        g_concat[((size_t)b * HW + p0 + pl) * CTOT + c] = __float2half(v);
        s += v;
    }
    red[t >> 6][c] = s;
    __syncthreads();
    if (t < 64)
        g_partial[((size_t)b * 144 + blockIdx.x) * 64 + t] =
            red[0][t] + red[1][t] + red[2][t] + red[3][t];
}

// ---------------------------------------------------------------------------
// Attention MLP per sample, with fused GAP-partial reduction for the newest
// 64 channels. grid(NB), block 128.
// ---------------------------------------------------------------------------
template <int CIN>
__global__ void attn_kernel(const float* __restrict__ aw1, const float* __restrict__ ab1,
                            const float* __restrict__ aw2, const float* __restrict__ ab2,
                            const float* __restrict__ bvec, int ntiles, int ch_off) {
    const int HID = CIN / 4;
    int b = blockIdx.x;
    int t = threadIdx.x;
    __shared__ float red[2][64];
    __shared__ float sp[CIN];
    __shared__ float sh[HID];
    __shared__ float sl[KK];
    __shared__ float sa[KK];

    {
        int ch = t & 63, grp = t >> 6;
        float s = 0.f;
        for (int tile = grp; tile < ntiles; tile += 2)
            s += g_partial[((size_t)b * 144 + tile) * 64 + ch];
        red[grp][ch] = s;
        __syncthreads();
        if (t < 64)
            g_pooled[b * CTOT + ch_off + t] = (red[0][t] + red[1][t]) * (1.f / (float)HW);
        __syncthreads();
    }

    for (int i = t; i < CIN; i += 128) sp[i] = g_pooled[b * CTOT + i];
    __syncthreads();
    if (t < HID) {
        float s = ab1[t];
        const float* row = aw1 + (size_t)t * CIN;
        for (int c = 0; c < CIN; c++) s += row[c] * sp[c];
        sh[t] = s > 0.f ? s : 0.f;
    }
    __syncthreads();
    if (t < KK) {
        float s = ab2[t];
        const float* row = aw2 + (size_t)t * HID;
        for (int j = 0; j < HID; j++) s += row[j] * sh[j];
        sl[t] = s;
    }
    __syncthreads();
    if (t == 0) {
        float m = sl[0];
        for (int k = 1; k < KK; k++) m = fmaxf(m, sl[k]);
        float den = 0.f;
        for (int k = 0; k < KK; k++) { float e = expf(sl[k] - m); sa[k] = e; den += e; }
        float inv = 1.f / den;
        for (int k = 0; k < KK; k++) { sa[k] *= inv; g_attn[b * KK + k] = sa[k]; }
    }
    __syncthreads();
    if (t < GC) {
        float s = 0.f;
        #pragma unroll
        for (int k = 0; k < KK; k++) s += sa[k] * bvec[k * GC + t];
        g_bk[b * GC + t] = s;
    }
}

// ---------------------------------------------------------------------------
// Batched weight mixing: thread owns (oc, c-pair), loads all 8 experts once,
// applies all 16 attention vectors. grid: (64*CIN/2)/128, block 128.
// ---------------------------------------------------------------------------
template <int CIN>
__global__ __launch_bounds__(128)
void mix2h_batched(const float* __restrict__ w) {
    __shared__ float s_attn[NB][KK];
    int t = threadIdx.x;
    if (t < NB * KK) s_attn[t / KK][t % KK] = g_attn[t];
    __syncthreads();

    int idx = blockIdx.x * 128 + t;
    const int NPC = CIN / 2;
    if (idx >= GC * NPC) return;
    int oc = idx / NPC;
    int cp = idx - oc * NPC;
    int cc = cp * 2;

    float wreg[KK][18];
    #pragma unroll
    for (int k = 0; k < KK; k++) {
        const float* src = w + (((size_t)k * GC + oc) * CIN + cc) * 9;
        #pragma unroll
        for (int j = 0; j < 18; j++) wreg[k][j] = src[j];
    }

    #pragma unroll 1
    for (int b = 0; b < NB; b++) {
        float a[KK];
        #pragma unroll
        for (int k = 0; k < KK; k++) a[k] = s_attn[b][k];
        float s[18];
        #pragma unroll
        for (int j = 0; j < 18; j++) {
            float v = 0.f;
            #pragma unroll
            for (int k = 0; k < KK; k++) v += a[k] * wreg[k][j];
            s[j] = v;
        }
        __half* dst = g_wk2h + (size_t)b * (9 * GC * CIN);
        #pragma unroll
        for (int tap = 0; tap < 9; tap++) {
            *(__half2*)&dst[(((size_t)tap * GC + oc) * CIN) + cc] =
                __floats2half2_rn(s[tap], s[tap + 9]);
        }
    }
}

// ---------------------------------------------------------------------------
// fp16 mma.sync conv, cp.async whole-chunk double-buffered pipeline.
// CTA: 512 pixels (16 rows x 32 cols) x 64 oc. 8 warps, EACH 64px x 64oc
// (M=64 warp tile -> 8 LDSM : 32 MMA per k16 step, ratio 4).
// grid (3, 6, NB), block 256, dynamic smem 2*95040 = 190080.
// ---------------------------------------------------------------------------
#define APAD 40
#define A_ROWS 612                                  // 18 x 34 halo rows
#define B_ROWS 576
#define A_BYTES (A_ROWS * APAD * 2)                 // 48960
#define STAGE_BYTES (A_BYTES + B_ROWS * APAD * 2)   // 95040
#define CONV_SMEM (2 * STAGE_BYTES)                 // 190080

__device__ __forceinline__ void mma_16816(float* c, const uint32_t* a, const uint32_t* b) {
    asm volatile(
        "mma.sync.aligned.m16n8k16.row.col.f32.f16.f16.f32 "
        "{%0,%1,%2,%3}, {%4,%5,%6,%7}, {%8,%9}, {%0,%1,%2,%3};"
        : "+f"(c[0]), "+f"(c[1]), "+f"(c[2]), "+f"(c[3])
        : "r"(a[0]), "r"(a[1]), "r"(a[2]), "r"(a[3]), "r"(b[0]), "r"(b[1]));
}

__device__ __forceinline__ void ldsm_x4(uint32_t* r, uint32_t saddr) {
    asm volatile("ldmatrix.sync.aligned.m8n8.x4.shared.b16 {%0,%1,%2,%3}, [%4];"
                 : "=r"(r[0]), "=r"(r[1]), "=r"(r[2]), "=r"(r[3]) : "r"(saddr));
}

__device__ __forceinline__ void cp_async16(uint32_t dst, const void* src, int src_sz) {
    asm volatile("cp.async.cg.shared.global [%0], [%1], 16, %2;"
                 :: "r"(dst), "l"(src), "r"(src_sz) : "memory");
}
#define CP_COMMIT() asm volatile("cp.async.commit_group;" ::: "memory")
#define CP_WAIT0()  asm volatile("cp.async.wait_group 0;" ::: "memory")

template <int CIN, bool FINAL>
__global__ __launch_bounds__(256, 1)
void conv_mma(float* __restrict__ dout, const float* __restrict__ xres, int out_ch_off) {
    extern __shared__ __align__(16) char dyn[];
    __shared__ float s_bias[64];
    __shared__ float s_red[8][64];

    const int t = threadIdx.x;
    const int lane = t & 31;
    const int wid = t >> 5;                 // 0..7 -> 2-row band within tile
    const int gx0 = blockIdx.x * 32;
    const int gy0 = blockIdx.y * 16;
    const int b = blockIdx.z;
    const int NC = CIN / 32;

    const uint32_t su = (uint32_t)__cvta_generic_to_shared(dyn);
    const __half* inb = g_concat + (size_t)b * HW * CTOT;
    const __half* wkb = g_wk2h + (size_t)b * (9 * GC * CIN);

    if (t < 64) s_bias[t] = g_bk[b * GC + t];

    // 4 m-tiles x 8 n-tiles x 4 = 128 accumulators
    float acc[4][8][4];
    #pragma unroll
    for (int mt = 0; mt < 4; mt++)
        #pragma unroll
        for (int nt = 0; nt < 8; nt++)
            #pragma unroll
            for (int q = 0; q < 4; q++) acc[mt][nt][q] = 0.f;

    auto issue_chunk = [&](int c0, int stage) {
        uint32_t sbase = su + stage * STAGE_BYTES;
        // A: 612 halo rows x 4 segs = 2448
        #pragma unroll
        for (int k = 0; k < 10; k++) {
            int i = t + k * 256;
            if (i < A_ROWS * 4) {
                int row = i >> 2, q = i & 3;
                int r = row / 34, cc = row - r * 34;
                int gy = gy0 + r - 1, gx = gx0 + cc - 1;
                bool ok = ((unsigned)gy < HH) && ((unsigned)gx < WW);
                const __half* src = ok ? (inb + (size_t)(gy * WW + gx) * CTOT + c0 + q * 8)
                                       : inb;
                cp_async16(sbase + (row * APAD + q * 8) * 2, src, ok ? 16 : 0);
            }
        }
        // B: 576 rows x 4 segs = 2304 = 9 * 256
        #pragma unroll
        for (int k = 0; k < 9; k++) {
            int i = t + k * 256;
            int row = i >> 2, q = i & 3;
            const __half* src = wkb + (size_t)row * CIN + c0 + q * 8;
            cp_async16(sbase + A_BYTES + (row * APAD + q * 8) * 2, src, 16);
        }
    };

    issue_chunk(0, 0);
    CP_COMMIT();

    const int a_m  = lane & 15;
    const int a_kh = lane >> 4;
    const int b_n  = (lane >> 4) * 8 + (lane & 7);
    const int b_kh = (lane >> 3) & 1;

    #pragma unroll 1
    for (int ic = 0; ic < NC; ic++) {
        const int s = ic & 1;
        const uint32_t sa_u = su + s * STAGE_BYTES;
        const uint32_t sb_u = sa_u + A_BYTES;

        CP_WAIT0();
        __syncthreads();     // stage s full; orders prior readers of s^1
        if (ic + 1 < NC) {
            issue_chunk((ic + 1) * 32, s ^ 1);
            CP_COMMIT();
        }

        #pragma unroll 1
        for (int tap = 0; tap < 9; tap++) {
            const int dy = tap / 3 - 1, dx = tap % 3 - 1;
            // warp covers rows wid*2, wid*2+1; m-tile mt covers pixels
            // mt*16..mt*16+15 -> image row wid*2 + (mt>>1), col (mt&1)*16..
            const uint32_t btap = sb_u + (tap * 64) * (APAD * 2);
            #pragma unroll
            for (int k16 = 0; k16 < 2; k16++) {
                uint32_t af[4][4];
                #pragma unroll
                for (int mt = 0; mt < 4; mt++) {
                    int irow = wid * 2 + (mt >> 1);            // image row in tile
                    int icol = (mt & 1) * 16;                  // col base of m16 tile
                    int arow = (irow + dy + 1) * 34 + icol + dx + 1 + a_m;
                    uint32_t addr = sa_u + 2 * (arow * APAD + k16 * 16 + a_kh * 8);
                    ldsm_x4(af[mt], addr);
                }
                uint32_t bf[8][2];
                #pragma unroll
                for (int j = 0; j < 4; j++) {
                    uint32_t r[4];
                    int n = j * 16 + b_n;
                    uint32_t addr = btap + 2 * (n * APAD + k16 * 16 + b_kh * 8);
                    ldsm_x4(r, addr);
                    bf[j * 2][0] = r[0]; bf[j * 2][1] = r[1];
                    bf[j * 2 + 1][0] = r[2]; bf[j * 2 + 1][1] = r[3];
                }
                #pragma unroll
                for (int mt = 0; mt < 4; mt++)
                    #pragma unroll
                    for (int nt = 0; nt < 8; nt++)
                        mma_16816(acc[mt][nt], af[mt], bf[nt]);
            }
        }
        // next iteration's top barrier orders stage overwrite
    }

    // epilogue (+ fused GAP partials)
    float sum0[8], sum1[8];
    #pragma unroll
    for (int nt = 0; nt < 8; nt++) { sum0[nt] = 0.f; sum1[nt] = 0.f; }

    #pragma unroll
    for (int mt = 0; mt < 4; mt++) {
        const int gy = gy0 + wid * 2 + (mt >> 1);
        #pragma unroll
        for (int hi = 0; hi < 2; hi++) {
            int gx = gx0 + (mt & 1) * 16 + (lane >> 2) + hi * 8;
            size_t pixidx = (size_t)gy * WW + gx;
            #pragma unroll
            for (int nt = 0; nt < 8; nt++) {
                int oc = nt * 8 + 2 * (lane & 3);
                float v0 = acc[mt][nt][hi * 2 + 0] + s_bias[oc];
                float v1 = acc[mt][nt][hi * 2 + 1] + s_bias[oc + 1];
                if (FINAL) {
                    dout[((size_t)b * GC + oc) * HW + pixidx] =
                        0.2f * v0 + xres[((size_t)b * GC + oc) * HW + pixidx];
                    dout[((size_t)b * GC + oc + 1) * HW + pixidx] =
                        0.2f * v1 + xres[((size_t)b * GC + oc + 1) * HW + pixidx];
                } else {
                    v0 = v0 >= 0.f ? v0 : 0.2f * v0;
                    v1 = v1 >= 0.f ? v1 : 0.2f * v1;
                    *(__half2*)&g_concat[((size_t)b * HW + pixidx) * CTOT + out_ch_off + oc] =
                        __floats2half2_rn(v0, v1);
                    sum0[nt] += v0;
                    sum1[nt] += v1;
                }
            }
        }
    }

    if (!FINAL) {
        #pragma unroll
        for (int nt = 0; nt < 8; nt++) {
            #pragma unroll
            for (int off = 16; off >= 4; off >>= 1) {
                sum0[nt] += __shfl_xor_sync(0xFFFFFFFFu, sum0[nt], off);
                sum1[nt] += __shfl_xor_sync(0xFFFFFFFFu, sum1[nt], off);
            }
        }
        if (lane < 4) {
            #pragma unroll
            for (int nt = 0; nt < 8; nt++) {
                int chl = nt * 8 + 2 * lane;
                s_red[wid][chl]     = sum0[nt];
                s_red[wid][chl + 1] = sum1[nt];
            }
        }
        __syncthreads();
        if (t < 64) {
            int tile = blockIdx.y * 3 + blockIdx.x;
            float s = 0.f;
            #pragma unroll
            for (int wv = 0; wv < 8; wv++) s += s_red[wv][t];
            g_partial[((size_t)b * 144 + tile) * 64 + t] = s;
        }
    }
}

// ---------------------------------------------------------------------------
// Host orchestration
// ---------------------------------------------------------------------------
extern "C" void kernel_launch(void* const* d_in, const int* in_sizes, int n_in,
                              void* d_out, int out_size) {
    const float* x = (const float*)d_in[0];
    const float *W[5], *Bv[5], *A1[5], *Ab1[5], *A2[5], *Ab2[5];
    for (int i = 0; i < 5; i++) {
        W[i]   = (const float*)d_in[1 + 6 * i + 0];
        Bv[i]  = (const float*)d_in[1 + 6 * i + 1];
        A1[i]  = (const float*)d_in[1 + 6 * i + 2];
        Ab1[i] = (const float*)d_in[1 + 6 * i + 3];
        A2[i]  = (const float*)d_in[1 + 6 * i + 4];
        Ab2[i] = (const float*)d_in[1 + 6 * i + 5];
    }
    float* out = (float*)d_out;

    cudaFuncSetAttribute(conv_mma<64,  false>, cudaFuncAttributeMaxDynamicSharedMemorySize, CONV_SMEM);
    cudaFuncSetAttribute(conv_mma<128, false>, cudaFuncAttributeMaxDynamicSharedMemorySize, CONV_SMEM);
    cudaFuncSetAttribute(conv_mma<192, false>, cudaFuncAttributeMaxDynamicSharedMemorySize, CONV_SMEM);
    cudaFuncSetAttribute(conv_mma<256, false>, cudaFuncAttributeMaxDynamicSharedMemorySize, CONV_SMEM);
    cudaFuncSetAttribute(conv_mma<320, true >, cudaFuncAttributeMaxDynamicSharedMemorySize, CONV_SMEM);

    dim3 cgrid(3, 6, NB);

    copyx_t<<<dim3(144, NB), 256>>>(x);

    // Layer 1 (cin=64)
    attn_kernel<64><<<NB, 128>>>(A1[0], Ab1[0], A2[0], Ab2[0], Bv[0], 144, 0);
    mix2h_batched<64><<<(GC * 32 + 127) / 128, 128>>>(W[0]);
    conv_mma<64, false><<<cgrid, 256, CONV_SMEM>>>(nullptr, nullptr, 64);

    // Layer 2 (cin=128)
    attn_kernel<128><<<NB, 128>>>(A1[1], Ab1[1], A2[1], Ab2[1], Bv[1], 18, 64);
    mix2h_batched<128><<<(GC * 64 + 127) / 128, 128>>>(W[1]);
    conv_mma<128, false><<<cgrid, 256, CONV_SMEM>>>(nullptr, nullptr, 128);

    // Layer 3 (cin=192)
    attn_kernel<192><<<NB, 128>>>(A1[2], Ab1[2], A2[2], Ab2[2], Bv[2], 18, 128);
    mix2h_batched<192><<<(GC * 96 + 127) / 128, 128>>>(W[2]);
    conv_mma<192, false><<<cgrid, 256, CONV_SMEM>>>(nullptr, nullptr, 192);

    // Layer 4 (cin=256)
    attn_kernel<256><<<NB, 128>>>(A1[3], Ab1[3], A2[3], Ab2[3], Bv[3], 18, 192);
    mix2h_batched<256><<<(GC * 128 + 127) / 128, 128>>>(W[3]);
    conv_mma<256, false><<<cgrid, 256, CONV_SMEM>>>(nullptr, nullptr, 256);

    // Layer 5 (cin=320) -> final output with fp32 residual from original x
    attn_kernel<320><<<NB, 128>>>(A1[4], Ab1[4], A2[4], Ab2[4], Bv[4], 18, 256);
    mix2h_batched<320><<<(GC * 160 + 127) / 128, 128>>>(W[4]);
    conv_mma<320, true><<<cgrid, 256, CONV_SMEM>>>(out, x, 0);
}